// round 15
// baseline (speedup 1.0000x reference)
#include <cuda_runtime.h>
#include <cuda.h>
#include <cuda_fp16.h>
#include <math.h>
#include <stdint.h>

#define Bn  2
#define Tn  2048
#define Dn  1024
#define Hn  16
#define HDn 64
#define Mn  (Bn * Tn)   // 4096

// -------- scratch (static device globals; no allocations allowed) --------
__device__ __half2 g_xb[(size_t)Mn * Dn / 2];            // x f16 [4096][1024]
__device__ __half2 g_Wqb[(size_t)Dn * Dn / 2];           // W f16 [k][n]
__device__ __half2 g_Wkb[(size_t)Dn * Dn / 2];
__device__ __half2 g_Wvb[(size_t)Dn * Dn / 2];
__device__ __half2 g_Wob[(size_t)Dn * Dn / 2];
__device__ unsigned g_Q[(size_t)Bn * Hn * Tn * HDn / 2]; // f16x2 [bh*T+t][32]
__device__ unsigned g_K[(size_t)Bn * Hn * Tn * HDn / 2];
__device__ unsigned g_V[(size_t)Bn * Hn * Tn * HDn / 2];
__device__ unsigned g_O[(size_t)Mn * Dn / 2];            // f16x2 [B*T][512]
__device__ float    g_P[(size_t)Mn * Dn];                // pre-LN fp32

// ---------------- helpers ----------------
__device__ __forceinline__ uint32_t s2u(const void* p) {
    return (uint32_t)__cvta_generic_to_shared(p);
}
__device__ __forceinline__ unsigned pkh(float a, float b) {
    __half2 t = __float22half2_rn(make_float2(a, b));
    return *(unsigned*)&t;
}
__device__ __forceinline__ unsigned hex2(unsigned x) {
    unsigned y;
    asm("ex2.approx.f16x2 %0, %1;" : "=r"(y) : "r"(x));
    return y;
}
// SW128 swizzle on byte offset within a tile of 128B rows
__device__ __forceinline__ uint32_t swz(uint32_t o) {
    return o ^ ((o >> 3) & 0x70);
}
// D += A(16x16) * B(16x8), f16 in, f32 accum
__device__ __forceinline__ void mma16(float* d, const unsigned* a,
                                      unsigned b0, unsigned b1) {
    asm volatile(
        "mma.sync.aligned.m16n8k16.row.col.f32.f16.f16.f32 "
        "{%0,%1,%2,%3},{%4,%5,%6,%7},{%8,%9},{%0,%1,%2,%3};"
        : "+f"(d[0]), "+f"(d[1]), "+f"(d[2]), "+f"(d[3])
        : "r"(a[0]), "r"(a[1]), "r"(a[2]), "r"(a[3]), "r"(b0), "r"(b1));
}
__device__ __forceinline__ void ldsm_x4(unsigned* r, uint32_t a) {
    asm volatile("ldmatrix.sync.aligned.m8n8.x4.shared.b16 {%0,%1,%2,%3}, [%4];"
        : "=r"(r[0]), "=r"(r[1]), "=r"(r[2]), "=r"(r[3]) : "r"(a));
}
__device__ __forceinline__ void ldsm_x4t(unsigned* r, uint32_t a) {
    asm volatile("ldmatrix.sync.aligned.m8n8.x4.trans.shared.b16 {%0,%1,%2,%3}, [%4];"
        : "=r"(r[0]), "=r"(r[1]), "=r"(r[2]), "=r"(r[3]) : "r"(a));
}
__device__ __forceinline__ void mbar_init(uint32_t m, uint32_t cnt) {
    asm volatile("mbarrier.init.shared.b64 [%0], %1;" :: "r"(m), "r"(cnt) : "memory");
}
__device__ __forceinline__ void mbar_expect(uint32_t m, uint32_t bytes) {
    asm volatile("mbarrier.arrive.expect_tx.shared.b64 _, [%0], %1;"
                 :: "r"(m), "r"(bytes) : "memory");
}
__device__ __forceinline__ void mbar_wait(uint32_t m, uint32_t parity) {
    asm volatile(
        "{\n\t.reg .pred P1;\n\t"
        "WAIT_%=:\n\t"
        "mbarrier.try_wait.parity.acquire.cta.shared::cta.b64 P1, [%0], %1, 0x989680;\n\t"
        "@P1 bra.uni DONE_%=;\n\t"
        "bra.uni WAIT_%=;\n\t"
        "DONE_%=:\n\t}"
        :: "r"(m), "r"(parity) : "memory");
}
__device__ __forceinline__ void tma2d(uint32_t dst, const CUtensorMap* tm,
                                      int x, int y, uint32_t mbar) {
    asm volatile(
        "cp.async.bulk.tensor.2d.shared::cta.global.tile.mbarrier::complete_tx::bytes "
        "[%0], [%1, {%2, %3}], [%4];"
        :: "r"(dst), "l"(tm), "r"(x), "r"(y), "r"(mbar) : "memory");
}

#define ONESH 0x3C003C00u    // f16x2 (1.0, 1.0)

// =========================================================================
// f16 conversion pre-pass: grid (1024,1,8). z 0..3 = quarters of x,
// z 4..7 = the four weights.
// =========================================================================
__global__ void __launch_bounds__(256) cvt_f16(
    const float* __restrict__ x,
    const float* __restrict__ wq, const float* __restrict__ wk,
    const float* __restrict__ wv, const float* __restrict__ wo)
{
    const float* src; __half2* dst; size_t base;
    const int z = blockIdx.z;
    if (z < 4) {
        src = x; dst = g_xb;
        base = (size_t)z * (Mn * Dn / 16);
    } else {
        switch (z) {
            case 4: src = wq; dst = g_Wqb; break;
            case 5: src = wk; dst = g_Wkb; break;
            case 6: src = wv; dst = g_Wvb; break;
            default: src = wo; dst = g_Wob; break;
        }
        base = 0;
    }
    size_t i = base + blockIdx.x * 256 + threadIdx.x;
    float4 v = ((const float4*)src)[i];
    dst[2 * i]     = __float22half2_rn(make_float2(v.x, v.y));
    dst[2 * i + 1] = __float22half2_rn(make_float2(v.z, v.w));
}

// =========================================================================
// f16 GEMM, 256m x 128n CTA tile, K-chunk 64, 4-stage TMA pipeline,
// 1 CTA/SM (255-reg budget). 256 threads = 8 warps (4m x 2n),
// warp tile 64m x 64n (acc[4][8][4] = 128 regs).
// Stage 48KB: A [256 m][64 k] SW128 (32KB) | B 2 x [64 k][64 n] SW128 (8KB).
// =========================================================================
#define G_STG 49152
#define GEMM_DSMEM (4 * G_STG + 1024)

__device__ __forceinline__ void gemm_main(
    const CUtensorMap* tmA, const CUtensorMap* tmB,
    const float* __restrict__ bias, const float* __restrict__ resid,
    unsigned* out_q, float* out_f, int mode, float scale)
{
    extern __shared__ char smraw[];
    char* smb = (char*)(((uintptr_t)smraw + 1023) & ~(uintptr_t)1023);
    __shared__ uint64_t mb[4];

    const int tid = threadIdx.x, lane = tid & 31, w = tid >> 5;
    const int g = lane >> 2, tig = lane & 3;
    const int wm = w & 3, wn = w >> 2;
    const int l15 = lane & 15, lhi = (lane >> 4) & 1;
    const int m0 = blockIdx.y * 256, n0 = blockIdx.x * 128;
    const uint32_t smu = s2u(smb);

    if (tid == 0)
        for (int s = 0; s < 4; s++) mbar_init(s2u(&mb[s]), 1);
    __syncthreads();
    if (tid == 0) {
        for (int s = 0; s < 3; s++) {       // chunks 0..2 -> slots 0..2
            uint32_t st = smu + s * G_STG;
            mbar_expect(s2u(&mb[s]), G_STG);
            tma2d(st,          tmA, s * 64,  m0,     s2u(&mb[s]));
            tma2d(st + 32768,  tmB, n0,      s * 64, s2u(&mb[s]));
            tma2d(st + 40960,  tmB, n0 + 64, s * 64, s2u(&mb[s]));
        }
    }

    float acc[4][8][4];
#pragma unroll
    for (int mt = 0; mt < 4; mt++)
#pragma unroll
        for (int nt = 0; nt < 8; nt++)
#pragma unroll
            for (int j = 0; j < 4; j++) acc[mt][nt][j] = 0.f;

    for (int c = 0; c < 16; c++) {
        mbar_wait(s2u(&mb[c & 3]), (c >> 2) & 1);
        __syncthreads();                    // data ready + slot (c-1)&3 free
        if (tid == 0 && c + 3 < 16) {
            int s = (c + 3) & 3;
            uint32_t st = smu + s * G_STG;
            mbar_expect(s2u(&mb[s]), G_STG);
            tma2d(st,          tmA, (c + 3) * 64, m0,           s2u(&mb[s]));
            tma2d(st + 32768,  tmB, n0,           (c + 3) * 64, s2u(&mb[s]));
            tma2d(st + 40960,  tmB, n0 + 64,      (c + 3) * 64, s2u(&mb[s]));
        }

        const uint32_t as_b = smu + (c & 3) * G_STG;
        const uint32_t bs_b = as_b + 32768 + wn * 8192;

#pragma unroll
        for (int kk = 0; kk < 4; kk++) {
            unsigned av[4][4];
#pragma unroll
            for (int mt = 0; mt < 4; mt++)
                ldsm_x4(av[mt], as_b + swz((wm * 64 + mt * 16 + l15) * 128
                                           + (kk * 16 + lhi * 8) * 2));
#pragma unroll
            for (int ntp = 0; ntp < 4; ntp++) {
                unsigned bv[4];
                ldsm_x4t(bv, bs_b + swz((kk * 16 + l15) * 128
                                        + (ntp * 16 + lhi * 8) * 2));
#pragma unroll
                for (int mt = 0; mt < 4; mt++) {
                    mma16(acc[mt][2 * ntp],     av[mt], bv[0], bv[1]);
                    mma16(acc[mt][2 * ntp + 1], av[mt], bv[2], bv[3]);
                }
            }
        }
    }

    // epilogue
#pragma unroll
    for (int mt = 0; mt < 4; mt++) {
#pragma unroll
        for (int nt = 0; nt < 8; nt++) {
            int r0 = m0 + wm * 64 + mt * 16 + g;
            int n = n0 + wn * 64 + nt * 8 + 2 * tig;
            float2 bv2 = *(const float2*)&bias[n];
            if (mode == 0) {
#pragma unroll
                for (int rp = 0; rp < 2; rp++) {
                    int r = r0 + rp * 8;
                    int bb = r >> 11, t = r & (Tn - 1);
                    int h = n >> 6, hd = n & 63;
                    float v0 = (acc[mt][nt][2 * rp]     + bv2.x) * scale;
                    float v1 = (acc[mt][nt][2 * rp + 1] + bv2.y) * scale;
                    out_q[(((size_t)(bb * Hn + h) * Tn + t) << 5) + (hd >> 1)] = pkh(v0, v1);
                }
            } else {
#pragma unroll
                for (int rp = 0; rp < 2; rp++) {
                    int r = r0 + rp * 8;
                    size_t off = (size_t)r * Dn + n;
                    float2 rv = *(const float2*)&resid[off];
                    float2 val = make_float2(acc[mt][nt][2 * rp] + bv2.x + rv.x,
                                             acc[mt][nt][2 * rp + 1] + bv2.y + rv.y);
                    *(float2*)&out_f[off] = val;
                }
            }
        }
    }
}

// Q is scaled by (1/8)*log2(e) so softmax can run in exp2 domain.
#define QSCALE 0.18033688f

__global__ void __launch_bounds__(256, 1) qkv_gemm(
    const __grid_constant__ CUtensorMap tmA,
    const __grid_constant__ CUtensorMap tmq,
    const __grid_constant__ CUtensorMap tmk,
    const __grid_constant__ CUtensorMap tmv,
    const float* __restrict__ bq, const float* __restrict__ bk,
    const float* __restrict__ bv)
{
    const CUtensorMap* tb; const float* b; unsigned* o; float scale;
    if (blockIdx.z == 0)      { tb = &tmq; b = bq; o = g_Q; scale = QSCALE; }
    else if (blockIdx.z == 1) { tb = &tmk; b = bk; o = g_K; scale = 1.f; }
    else                      { tb = &tmv; b = bv; o = g_V; scale = 1.f; }
    gemm_main(&tmA, tb, b, nullptr, o, nullptr, 0, scale);
}

__global__ void __launch_bounds__(256, 1) oproj_gemm(
    const __grid_constant__ CUtensorMap tmA,
    const __grid_constant__ CUtensorMap tmW,
    const float* __restrict__ bo, const float* __restrict__ resid)
{
    gemm_main(&tmA, &tmW, bo, resid, nullptr, g_P, 1, 1.f);
}

// =========================================================================
// f16 flash attention, TMA loads, 4-stage pipeline (unchanged from R14).
// =========================================================================
#define A_STG 16384
#define ATT_DSMEM (16384 + 4 * A_STG + 1024)

__global__ void __launch_bounds__(256, 2) attn_tc(
    const __grid_constant__ CUtensorMap tmQ,
    const __grid_constant__ CUtensorMap tmK,
    const __grid_constant__ CUtensorMap tmV)
{
    extern __shared__ char smraw[];
    char* smb = (char*)(((uintptr_t)smraw + 1023) & ~(uintptr_t)1023);
    __shared__ uint64_t mbq, mb[4];

    const int tid = threadIdx.x, lane = tid & 31, w = tid >> 5;
    const int l15 = lane & 15, lhi = (lane >> 4) & 1, l8 = (lane >> 3) & 1;
    const int g = lane >> 2, tig = lane & 3;
    const int bh = blockIdx.y;
    const int q0 = blockIdx.x << 7;
    const int b = bh >> 4, h = bh & 15;
    const int rb = w * 16;
    const int krow0 = bh * Tn;
    const uint32_t smu = s2u(smb);
    const uint32_t qs_b = smu, buf = smu + 16384;

    if (tid == 0) {
        mbar_init(s2u(&mbq), 1);
        for (int s = 0; s < 4; s++) mbar_init(s2u(&mb[s]), 1);
    }
    __syncthreads();
    if (tid == 0) {
        mbar_expect(s2u(&mbq), 16384);
        tma2d(qs_b, &tmQ, 0, krow0 + q0, s2u(&mbq));
        for (int s = 0; s < 3; s++) {
            uint32_t st = buf + s * A_STG;
            mbar_expect(s2u(&mb[s]), A_STG);
            tma2d(st,        &tmK, 0, krow0 + s * 64, s2u(&mb[s]));
            tma2d(st + 8192, &tmV, 0, krow0 + s * 64, s2u(&mb[s]));
        }
    }

    mbar_wait(s2u(&mbq), 0);
    unsigned qa[4][4];
#pragma unroll
    for (int kk = 0; kk < 4; kk++)
        ldsm_x4(qa[kk], qs_b + swz((rb + l15) * 128 + (kk * 16 + lhi * 8) * 2));

    float oacc[8][4], lacc[4];
#pragma unroll
    for (int nt = 0; nt < 8; nt++)
#pragma unroll
        for (int j = 0; j < 4; j++) oacc[nt][j] = 0.f;
#pragma unroll
    for (int j = 0; j < 4; j++) lacc[j] = 0.f;

    for (int it = 0; it < 32; it++) {
        mbar_wait(s2u(&mb[it & 3]), (it >> 2) & 1);
        __syncthreads();
        if (tid == 0 && it + 3 < 32) {
            int s = (it + 3) & 3;
            uint32_t st = buf + s * A_STG;
            mbar_expect(s2u(&mb[s]), A_STG);
            tma2d(st,        &tmK, 0, krow0 + (it + 3) * 64, s2u(&mb[s]));
            tma2d(st + 8192, &tmV, 0, krow0 + (it + 3) * 64, s2u(&mb[s]));
        }

        const uint32_t ks_b = buf + (it & 3) * A_STG;
        const uint32_t vs_b = ks_b + 8192;

        float sacc[8][4];
#pragma unroll
        for (int nt = 0; nt < 8; nt++)
#pragma unroll
            for (int j = 0; j < 4; j++) sacc[nt][j] = -8.0f;

#pragma unroll
        for (int kk = 0; kk < 4; kk++) {
#pragma unroll
            for (int ntp = 0; ntp < 4; ntp++) {
                unsigned kb[4];
                ldsm_x4(kb, ks_b + swz((ntp * 16 + (lane & 7) + lhi * 8) * 128
                                       + (kk * 16 + l8 * 8) * 2));
                mma16(sacc[2 * ntp],     qa[kk], kb[0], kb[1]);
                mma16(sacc[2 * ntp + 1], qa[kk], kb[2], kb[3]);
            }
        }

#pragma unroll
        for (int kk = 0; kk < 4; kk++) {
            unsigned pa[4];
            pa[0] = hex2(pkh(sacc[2 * kk][0],     sacc[2 * kk][1]));
            pa[1] = hex2(pkh(sacc[2 * kk][2],     sacc[2 * kk][3]));
            pa[2] = hex2(pkh(sacc[2 * kk + 1][0], sacc[2 * kk + 1][1]));
            pa[3] = hex2(pkh(sacc[2 * kk + 1][2], sacc[2 * kk + 1][3]));
            mma16(lacc, pa, ONESH, ONESH);
#pragma unroll
            for (int ntp = 0; ntp < 4; ntp++) {
                unsigned vb[4];
                ldsm_x4t(vb, vs_b + swz((kk * 16 + l15) * 128
                                        + (ntp * 16 + lhi * 8) * 2));
                mma16(oacc[2 * ntp],     pa, vb[0], vb[1]);
                mma16(oacc[2 * ntp + 1], pa, vb[2], vb[3]);
            }
        }
    }

    float i0 = 1.f / lacc[0], i1 = 1.f / lacc[2];
    int gr0 = b * Tn + q0 + rb + g;
#pragma unroll
    for (int nt = 0; nt < 8; nt++) {
        int col = h * HDn + nt * 8 + 2 * tig;
        g_O[(size_t)gr0 * 512 + (col >> 1)] =
            pkh(oacc[nt][0] * i0, oacc[nt][1] * i0);
        g_O[(size_t)(gr0 + 8) * 512 + (col >> 1)] =
            pkh(oacc[nt][2] * i1, oacc[nt][3] * i1);
    }
}

// =========================================================================
// LayerNorm: warp-per-row (R14). Grid = Mn/8 = 512, 256 threads.
// =========================================================================
__global__ void __launch_bounds__(256) ln_kernel(
    const float* __restrict__ P, const float* __restrict__ gw,
    const float* __restrict__ gb, float* __restrict__ out)
{
    const int lane = threadIdx.x & 31;
    const int row = blockIdx.x * 8 + (threadIdx.x >> 5);
    const float4* src = (const float4*)(P + (size_t)row * Dn);

    float4 v[8];
    float s = 0.f, ss = 0.f;
#pragma unroll
    for (int i = 0; i < 8; i++) {
        v[i] = src[lane + 32 * i];
        s  += v[i].x + v[i].y + v[i].z + v[i].w;
        ss += v[i].x * v[i].x + v[i].y * v[i].y
            + v[i].z * v[i].z + v[i].w * v[i].w;
    }
#pragma unroll
    for (int off = 16; off; off >>= 1) {
        s  += __shfl_xor_sync(0xffffffffu, s, off);
        ss += __shfl_xor_sync(0xffffffffu, ss, off);
    }
    const float mu  = s * (1.0f / Dn);
    const float var = ss * (1.0f / Dn) - mu * mu;
    const float rs  = rsqrtf(var + 1e-5f);

    float4* dst = (float4*)(out + (size_t)row * Dn);
#pragma unroll
    for (int i = 0; i < 8; i++) {
        const float4 gv = ((const float4*)gw)[lane + 32 * i];
        const float4 bv = ((const float4*)gb)[lane + 32 * i];
        float4 r;
        r.x = (v[i].x - mu) * rs * gv.x + bv.x;
        r.y = (v[i].y - mu) * rs * gv.y + bv.y;
        r.z = (v[i].z - mu) * rs * gv.z + bv.z;
        r.w = (v[i].w - mu) * rs * gv.w + bv.w;
        dst[lane + 32 * i] = r;
    }
}

// =========================================================================
// Host
// =========================================================================
typedef CUresult (*PFN_tmencode)(
    CUtensorMap*, CUtensorMapDataType, cuuint32_t, void*,
    const cuuint64_t*, const cuuint64_t*, const cuuint32_t*, const cuuint32_t*,
    CUtensorMapInterleave, CUtensorMapSwizzle, CUtensorMapL2promotion,
    CUtensorMapFloatOOBfill);

static void mkmap_f16(PFN_tmencode enc, CUtensorMap* tm, const void* ptr,
                      unsigned long long d0, unsigned long long d1,
                      unsigned long long stride_bytes, unsigned b0, unsigned b1)
{
    cuuint64_t dims[2] = {(cuuint64_t)d0, (cuuint64_t)d1};
    cuuint64_t str[1]  = {(cuuint64_t)stride_bytes};
    cuuint32_t box[2]  = {b0, b1};
    cuuint32_t es[2]   = {1, 1};
    enc(tm, CU_TENSOR_MAP_DATA_TYPE_FLOAT16, 2, (void*)ptr, dims, str, box, es,
        CU_TENSOR_MAP_INTERLEAVE_NONE, CU_TENSOR_MAP_SWIZZLE_128B,
        CU_TENSOR_MAP_L2_PROMOTION_L2_128B, CU_TENSOR_MAP_FLOAT_OOB_FILL_NONE);
}

extern "C" void kernel_launch(void* const* d_in, const int* in_sizes, int n_in,
                              void* d_out, int out_size)
{
    const float* x  = (const float*)d_in[0];
    const float* Wq = (const float*)d_in[1];
    const float* bq = (const float*)d_in[2];
    const float* Wk = (const float*)d_in[3];
    const float* bk = (const float*)d_in[4];
    const float* Wv = (const float*)d_in[5];
    const float* bv = (const float*)d_in[6];
    const float* Wo = (const float*)d_in[7];
    const float* bo = (const float*)d_in[8];
    const float* lg = (const float*)d_in[9];
    const float* lb = (const float*)d_in[10];
    float* out = (float*)d_out;

    void *gxb, *gwq, *gwk, *gwv, *gwo, *gq, *gk, *gv, *go, *gp;
    cudaGetSymbolAddress(&gxb, g_xb);
    cudaGetSymbolAddress(&gwq, g_Wqb);
    cudaGetSymbolAddress(&gwk, g_Wkb);
    cudaGetSymbolAddress(&gwv, g_Wvb);
    cudaGetSymbolAddress(&gwo, g_Wob);
    cudaGetSymbolAddress(&gq,  g_Q);
    cudaGetSymbolAddress(&gk,  g_K);
    cudaGetSymbolAddress(&gv,  g_V);
    cudaGetSymbolAddress(&go,  g_O);
    cudaGetSymbolAddress(&gp,  g_P);

    void* fp = nullptr;
    cudaDriverEntryPointQueryResult st;
    cudaGetDriverEntryPointByVersion("cuTensorMapEncodeTiled", &fp, 12000,
                                     cudaEnableDefault, &st);
    PFN_tmencode enc = (PFN_tmencode)fp;

    CUtensorMap tmX, tmO, tmWq, tmWk, tmWv, tmWo, tmQ, tmK, tmV;
    // activations [4096 m][1024 k] f16: box 64k x 256m
    mkmap_f16(enc, &tmX, gxb, 1024, 4096, 2048ULL, 64, 256);
    mkmap_f16(enc, &tmO, go,  1024, 4096, 2048ULL, 64, 256);
    // weights [1024 k][1024 n] f16: box 64n x 64k
    mkmap_f16(enc, &tmWq, gwq, 1024, 1024, 2048ULL, 64, 64);
    mkmap_f16(enc, &tmWk, gwk, 1024, 1024, 2048ULL, 64, 64);
    mkmap_f16(enc, &tmWv, gwv, 1024, 1024, 2048ULL, 64, 64);
    mkmap_f16(enc, &tmWo, gwo, 1024, 1024, 2048ULL, 64, 64);
    // Q/K/V [65536 rows][64 d] f16 (stride 128B)
    mkmap_f16(enc, &tmQ, gq, 64, (unsigned long long)Bn * Hn * Tn, 128ULL, 64, 128);
    mkmap_f16(enc, &tmK, gk, 64, (unsigned long long)Bn * Hn * Tn, 128ULL, 64, 64);
    mkmap_f16(enc, &tmV, gv, 64, (unsigned long long)Bn * Hn * Tn, 128ULL, 64, 64);

    cudaFuncSetAttribute(qkv_gemm, cudaFuncAttributeMaxDynamicSharedMemorySize,
                         GEMM_DSMEM);
    cudaFuncSetAttribute(oproj_gemm, cudaFuncAttributeMaxDynamicSharedMemorySize,
                         GEMM_DSMEM);
    cudaFuncSetAttribute(attn_tc, cudaFuncAttributeMaxDynamicSharedMemorySize,
                         ATT_DSMEM);

    cvt_f16<<<dim3(1024, 1, 8), 256>>>(x, Wq, Wk, Wv, Wo);

    qkv_gemm<<<dim3(Dn / 128, Mn / 256, 3), 256, GEMM_DSMEM>>>(
        tmX, tmWq, tmWk, tmWv, bq, bk, bv);

    attn_tc<<<dim3(Tn / 128, Bn * Hn), 256, ATT_DSMEM>>>(tmQ, tmK, tmV);

    oproj_gemm<<<dim3(Dn / 128, Mn / 256), 256, GEMM_DSMEM>>>(tmO, tmWo, bo, x);

    ln_kernel<<<Mn / 8, 256>>>((const float*)gp, lg, lb, out);
}

// round 16
// speedup vs baseline: 1.0361x; 1.0361x over previous
#include <cuda_runtime.h>
#include <cuda.h>
#include <cuda_fp16.h>
#include <math.h>
#include <stdint.h>

#define Bn  2
#define Tn  2048
#define Dn  1024
#define Hn  16
#define HDn 64
#define Mn  (Bn * Tn)   // 4096

// -------- scratch (static device globals; no allocations allowed) --------
__device__ __half2 g_xb[(size_t)Mn * Dn / 2];            // x f16 [4096][1024]
__device__ __half2 g_Wqb[(size_t)Dn * Dn / 2];           // W f16 [k][n]
__device__ __half2 g_Wkb[(size_t)Dn * Dn / 2];
__device__ __half2 g_Wvb[(size_t)Dn * Dn / 2];
__device__ __half2 g_Wob[(size_t)Dn * Dn / 2];
__device__ unsigned g_Q[(size_t)Bn * Hn * Tn * HDn / 2]; // f16x2 [bh*T+t][32]
__device__ unsigned g_K[(size_t)Bn * Hn * Tn * HDn / 2];
__device__ unsigned g_V[(size_t)Bn * Hn * Tn * HDn / 2];
__device__ unsigned g_O[(size_t)Mn * Dn / 2];            // f16x2 [B*T][512]
__device__ float    g_P[(size_t)Mn * Dn];                // pre-LN fp32

// ---------------- helpers ----------------
__device__ __forceinline__ uint32_t s2u(const void* p) {
    return (uint32_t)__cvta_generic_to_shared(p);
}
__device__ __forceinline__ unsigned pkh(float a, float b) {
    __half2 t = __float22half2_rn(make_float2(a, b));
    return *(unsigned*)&t;
}
__device__ __forceinline__ unsigned hex2(unsigned x) {
    unsigned y;
    asm("ex2.approx.f16x2 %0, %1;" : "=r"(y) : "r"(x));
    return y;
}
// SW128 swizzle on byte offset within a tile of 128B rows
__device__ __forceinline__ uint32_t swz(uint32_t o) {
    return o ^ ((o >> 3) & 0x70);
}
// D += A(16x16) * B(16x8), f16 in, f32 accum
__device__ __forceinline__ void mma16(float* d, const unsigned* a,
                                      unsigned b0, unsigned b1) {
    asm volatile(
        "mma.sync.aligned.m16n8k16.row.col.f32.f16.f16.f32 "
        "{%0,%1,%2,%3},{%4,%5,%6,%7},{%8,%9},{%0,%1,%2,%3};"
        : "+f"(d[0]), "+f"(d[1]), "+f"(d[2]), "+f"(d[3])
        : "r"(a[0]), "r"(a[1]), "r"(a[2]), "r"(a[3]), "r"(b0), "r"(b1));
}
__device__ __forceinline__ void ldsm_x4(unsigned* r, uint32_t a) {
    asm volatile("ldmatrix.sync.aligned.m8n8.x4.shared.b16 {%0,%1,%2,%3}, [%4];"
        : "=r"(r[0]), "=r"(r[1]), "=r"(r[2]), "=r"(r[3]) : "r"(a));
}
__device__ __forceinline__ void ldsm_x4t(unsigned* r, uint32_t a) {
    asm volatile("ldmatrix.sync.aligned.m8n8.x4.trans.shared.b16 {%0,%1,%2,%3}, [%4];"
        : "=r"(r[0]), "=r"(r[1]), "=r"(r[2]), "=r"(r[3]) : "r"(a));
}
__device__ __forceinline__ void mbar_init(uint32_t m, uint32_t cnt) {
    asm volatile("mbarrier.init.shared.b64 [%0], %1;" :: "r"(m), "r"(cnt) : "memory");
}
__device__ __forceinline__ void mbar_expect(uint32_t m, uint32_t bytes) {
    asm volatile("mbarrier.arrive.expect_tx.shared.b64 _, [%0], %1;"
                 :: "r"(m), "r"(bytes) : "memory");
}
__device__ __forceinline__ void mbar_wait(uint32_t m, uint32_t parity) {
    asm volatile(
        "{\n\t.reg .pred P1;\n\t"
        "WAIT_%=:\n\t"
        "mbarrier.try_wait.parity.acquire.cta.shared::cta.b64 P1, [%0], %1, 0x989680;\n\t"
        "@P1 bra.uni DONE_%=;\n\t"
        "bra.uni WAIT_%=;\n\t"
        "DONE_%=:\n\t}"
        :: "r"(m), "r"(parity) : "memory");
}
__device__ __forceinline__ void tma2d(uint32_t dst, const CUtensorMap* tm,
                                      int x, int y, uint32_t mbar) {
    asm volatile(
        "cp.async.bulk.tensor.2d.shared::cta.global.tile.mbarrier::complete_tx::bytes "
        "[%0], [%1, {%2, %3}], [%4];"
        :: "r"(dst), "l"(tm), "r"(x), "r"(y), "r"(mbar) : "memory");
}

#define ONESH 0x3C003C00u    // f16x2 (1.0, 1.0)

// =========================================================================
// f16 conversion pre-pass: grid (1024,1,8). z 0..3 = quarters of x,
// z 4..7 = the four weights.
// =========================================================================
__global__ void __launch_bounds__(256) cvt_f16(
    const float* __restrict__ x,
    const float* __restrict__ wq, const float* __restrict__ wk,
    const float* __restrict__ wv, const float* __restrict__ wo)
{
    const float* src; __half2* dst; size_t base;
    const int z = blockIdx.z;
    if (z < 4) {
        src = x; dst = g_xb;
        base = (size_t)z * (Mn * Dn / 16);
    } else {
        switch (z) {
            case 4: src = wq; dst = g_Wqb; break;
            case 5: src = wk; dst = g_Wkb; break;
            case 6: src = wv; dst = g_Wvb; break;
            default: src = wo; dst = g_Wob; break;
        }
        base = 0;
    }
    size_t i = base + blockIdx.x * 256 + threadIdx.x;
    float4 v = ((const float4*)src)[i];
    dst[2 * i]     = __float22half2_rn(make_float2(v.x, v.y));
    dst[2 * i + 1] = __float22half2_rn(make_float2(v.z, v.w));
}

// =========================================================================
// f16 GEMM, 256m x 128n CTA tile, K-chunk 128, 2-stage TMA pipeline.
// 512 threads = 16 warps (8m x 2n), warp tile 32m x 64n (acc 64 regs),
// 4 warps per SMSP for latency hiding. 1 CTA/SM (192KB smem).
// Stage 96KB: A 2 k-halves [256 m][64 k] SW128 (32KB each) |
//             B 4 tiles [64 k][64 n] SW128 (8KB each, khalf-major).
// Only 8 barrier/wait events per CTA.
// =========================================================================
#define G_STG 98304
#define GEMM_DSMEM (2 * G_STG + 1024)

__device__ __forceinline__ void gemm_issue(
    uint32_t st, const CUtensorMap* tmA, const CUtensorMap* tmB,
    int m0, int n0, int k0, uint32_t mbs)
{
    mbar_expect(mbs, G_STG);
    tma2d(st,          tmA, k0,      m0, mbs);
    tma2d(st + 32768,  tmA, k0 + 64, m0, mbs);
    tma2d(st + 65536,  tmB, n0,      k0,      mbs);
    tma2d(st + 73728,  tmB, n0 + 64, k0,      mbs);
    tma2d(st + 81920,  tmB, n0,      k0 + 64, mbs);
    tma2d(st + 90112,  tmB, n0 + 64, k0 + 64, mbs);
}

__device__ __forceinline__ void gemm_main(
    const CUtensorMap* tmA, const CUtensorMap* tmB,
    const float* __restrict__ bias, const float* __restrict__ resid,
    unsigned* out_q, float* out_f, int mode, float scale)
{
    extern __shared__ char smraw[];
    char* smb = (char*)(((uintptr_t)smraw + 1023) & ~(uintptr_t)1023);
    __shared__ uint64_t mb[2];

    const int tid = threadIdx.x, lane = tid & 31, w = tid >> 5;
    const int g = lane >> 2, tig = lane & 3;
    const int wm = w & 7, wn = w >> 3;
    const int l15 = lane & 15, lhi = (lane >> 4) & 1;
    const int m0 = blockIdx.y * 256, n0 = blockIdx.x * 128;
    const uint32_t smu = s2u(smb);

    if (tid == 0) {
        mbar_init(s2u(&mb[0]), 1);
        mbar_init(s2u(&mb[1]), 1);
    }
    __syncthreads();
    if (tid == 0)
        gemm_issue(smu, tmA, tmB, m0, n0, 0, s2u(&mb[0]));   // chunk 0 -> slot 0

    float acc[2][8][4];
#pragma unroll
    for (int mt = 0; mt < 2; mt++)
#pragma unroll
        for (int nt = 0; nt < 8; nt++)
#pragma unroll
            for (int j = 0; j < 4; j++) acc[mt][nt][j] = 0.f;

    for (int c = 0; c < 8; c++) {
        mbar_wait(s2u(&mb[c & 1]), (c >> 1) & 1);
        __syncthreads();                 // all warps done with chunk c-1
        if (tid == 0 && c + 1 < 8)       // slot (c+1)&1 is free now
            gemm_issue(smu + ((c + 1) & 1) * G_STG, tmA, tmB,
                       m0, n0, (c + 1) * 128, s2u(&mb[(c + 1) & 1]));

        const uint32_t as_b = smu + (c & 1) * G_STG;

#pragma unroll
        for (int kk = 0; kk < 8; kk++) {
            const int kh = kk >> 2, kw = kk & 3;
            const uint32_t a_base = as_b + kh * 32768;
            const uint32_t b_base = as_b + 65536 + kh * 16384 + wn * 8192;

            unsigned av[2][4];
#pragma unroll
            for (int mt = 0; mt < 2; mt++)
                ldsm_x4(av[mt], a_base + swz((wm * 32 + mt * 16 + l15) * 128
                                             + (kw * 16 + lhi * 8) * 2));
#pragma unroll
            for (int ntp = 0; ntp < 4; ntp++) {
                unsigned bv[4];
                ldsm_x4t(bv, b_base + swz((kw * 16 + l15) * 128
                                          + (ntp * 16 + lhi * 8) * 2));
                mma16(acc[0][2 * ntp],     av[0], bv[0], bv[1]);
                mma16(acc[1][2 * ntp],     av[1], bv[0], bv[1]);
                mma16(acc[0][2 * ntp + 1], av[0], bv[2], bv[3]);
                mma16(acc[1][2 * ntp + 1], av[1], bv[2], bv[3]);
            }
        }
    }

    // epilogue
#pragma unroll
    for (int mt = 0; mt < 2; mt++) {
#pragma unroll
        for (int nt = 0; nt < 8; nt++) {
            int r0 = m0 + wm * 32 + mt * 16 + g;
            int n = n0 + wn * 64 + nt * 8 + 2 * tig;
            float2 bv2 = *(const float2*)&bias[n];
            if (mode == 0) {
#pragma unroll
                for (int rp = 0; rp < 2; rp++) {
                    int r = r0 + rp * 8;
                    int bb = r >> 11, t = r & (Tn - 1);
                    int h = n >> 6, hd = n & 63;
                    float v0 = (acc[mt][nt][2 * rp]     + bv2.x) * scale;
                    float v1 = (acc[mt][nt][2 * rp + 1] + bv2.y) * scale;
                    out_q[(((size_t)(bb * Hn + h) * Tn + t) << 5) + (hd >> 1)] = pkh(v0, v1);
                }
            } else {
#pragma unroll
                for (int rp = 0; rp < 2; rp++) {
                    int r = r0 + rp * 8;
                    size_t off = (size_t)r * Dn + n;
                    float2 rv = *(const float2*)&resid[off];
                    float2 val = make_float2(acc[mt][nt][2 * rp] + bv2.x + rv.x,
                                             acc[mt][nt][2 * rp + 1] + bv2.y + rv.y);
                    *(float2*)&out_f[off] = val;
                }
            }
        }
    }
}

// Q is scaled by (1/8)*log2(e) so softmax can run in exp2 domain.
#define QSCALE 0.18033688f

__global__ void __launch_bounds__(512, 1) qkv_gemm(
    const __grid_constant__ CUtensorMap tmA,
    const __grid_constant__ CUtensorMap tmq,
    const __grid_constant__ CUtensorMap tmk,
    const __grid_constant__ CUtensorMap tmv,
    const float* __restrict__ bq, const float* __restrict__ bk,
    const float* __restrict__ bv)
{
    const CUtensorMap* tb; const float* b; unsigned* o; float scale;
    if (blockIdx.z == 0)      { tb = &tmq; b = bq; o = g_Q; scale = QSCALE; }
    else if (blockIdx.z == 1) { tb = &tmk; b = bk; o = g_K; scale = 1.f; }
    else                      { tb = &tmv; b = bv; o = g_V; scale = 1.f; }
    gemm_main(&tmA, tb, b, nullptr, o, nullptr, 0, scale);
}

__global__ void __launch_bounds__(512, 1) oproj_gemm(
    const __grid_constant__ CUtensorMap tmA,
    const __grid_constant__ CUtensorMap tmW,
    const float* __restrict__ bo, const float* __restrict__ resid)
{
    gemm_main(&tmA, &tmW, bo, resid, nullptr, g_P, 1, 1.f);
}

// =========================================================================
// f16 flash attention, TMA loads, 4-stage pipeline (byte-identical R14).
// =========================================================================
#define A_STG 16384
#define ATT_DSMEM (16384 + 4 * A_STG + 1024)

__global__ void __launch_bounds__(256, 2) attn_tc(
    const __grid_constant__ CUtensorMap tmQ,
    const __grid_constant__ CUtensorMap tmK,
    const __grid_constant__ CUtensorMap tmV)
{
    extern __shared__ char smraw[];
    char* smb = (char*)(((uintptr_t)smraw + 1023) & ~(uintptr_t)1023);
    __shared__ uint64_t mbq, mb[4];

    const int tid = threadIdx.x, lane = tid & 31, w = tid >> 5;
    const int l15 = lane & 15, lhi = (lane >> 4) & 1, l8 = (lane >> 3) & 1;
    const int g = lane >> 2, tig = lane & 3;
    const int bh = blockIdx.y;
    const int q0 = blockIdx.x << 7;
    const int b = bh >> 4, h = bh & 15;
    const int rb = w * 16;
    const int krow0 = bh * Tn;
    const uint32_t smu = s2u(smb);
    const uint32_t qs_b = smu, buf = smu + 16384;

    if (tid == 0) {
        mbar_init(s2u(&mbq), 1);
        for (int s = 0; s < 4; s++) mbar_init(s2u(&mb[s]), 1);
    }
    __syncthreads();
    if (tid == 0) {
        mbar_expect(s2u(&mbq), 16384);
        tma2d(qs_b, &tmQ, 0, krow0 + q0, s2u(&mbq));
        for (int s = 0; s < 3; s++) {
            uint32_t st = buf + s * A_STG;
            mbar_expect(s2u(&mb[s]), A_STG);
            tma2d(st,        &tmK, 0, krow0 + s * 64, s2u(&mb[s]));
            tma2d(st + 8192, &tmV, 0, krow0 + s * 64, s2u(&mb[s]));
        }
    }

    mbar_wait(s2u(&mbq), 0);
    unsigned qa[4][4];
#pragma unroll
    for (int kk = 0; kk < 4; kk++)
        ldsm_x4(qa[kk], qs_b + swz((rb + l15) * 128 + (kk * 16 + lhi * 8) * 2));

    float oacc[8][4], lacc[4];
#pragma unroll
    for (int nt = 0; nt < 8; nt++)
#pragma unroll
        for (int j = 0; j < 4; j++) oacc[nt][j] = 0.f;
#pragma unroll
    for (int j = 0; j < 4; j++) lacc[j] = 0.f;

    for (int it = 0; it < 32; it++) {
        mbar_wait(s2u(&mb[it & 3]), (it >> 2) & 1);
        __syncthreads();
        if (tid == 0 && it + 3 < 32) {
            int s = (it + 3) & 3;
            uint32_t st = buf + s * A_STG;
            mbar_expect(s2u(&mb[s]), A_STG);
            tma2d(st,        &tmK, 0, krow0 + (it + 3) * 64, s2u(&mb[s]));
            tma2d(st + 8192, &tmV, 0, krow0 + (it + 3) * 64, s2u(&mb[s]));
        }

        const uint32_t ks_b = buf + (it & 3) * A_STG;
        const uint32_t vs_b = ks_b + 8192;

        float sacc[8][4];
#pragma unroll
        for (int nt = 0; nt < 8; nt++)
#pragma unroll
            for (int j = 0; j < 4; j++) sacc[nt][j] = -8.0f;

#pragma unroll
        for (int kk = 0; kk < 4; kk++) {
#pragma unroll
            for (int ntp = 0; ntp < 4; ntp++) {
                unsigned kb[4];
                ldsm_x4(kb, ks_b + swz((ntp * 16 + (lane & 7) + lhi * 8) * 128
                                       + (kk * 16 + l8 * 8) * 2));
                mma16(sacc[2 * ntp],     qa[kk], kb[0], kb[1]);
                mma16(sacc[2 * ntp + 1], qa[kk], kb[2], kb[3]);
            }
        }

#pragma unroll
        for (int kk = 0; kk < 4; kk++) {
            unsigned pa[4];
            pa[0] = hex2(pkh(sacc[2 * kk][0],     sacc[2 * kk][1]));
            pa[1] = hex2(pkh(sacc[2 * kk][2],     sacc[2 * kk][3]));
            pa[2] = hex2(pkh(sacc[2 * kk + 1][0], sacc[2 * kk + 1][1]));
            pa[3] = hex2(pkh(sacc[2 * kk + 1][2], sacc[2 * kk + 1][3]));
            mma16(lacc, pa, ONESH, ONESH);
#pragma unroll
            for (int ntp = 0; ntp < 4; ntp++) {
                unsigned vb[4];
                ldsm_x4t(vb, vs_b + swz((kk * 16 + l15) * 128
                                        + (ntp * 16 + lhi * 8) * 2));
                mma16(oacc[2 * ntp],     pa, vb[0], vb[1]);
                mma16(oacc[2 * ntp + 1], pa, vb[2], vb[3]);
            }
        }
    }

    float i0 = 1.f / lacc[0], i1 = 1.f / lacc[2];
    int gr0 = b * Tn + q0 + rb + g;
#pragma unroll
    for (int nt = 0; nt < 8; nt++) {
        int col = h * HDn + nt * 8 + 2 * tig;
        g_O[(size_t)gr0 * 512 + (col >> 1)] =
            pkh(oacc[nt][0] * i0, oacc[nt][1] * i0);
        g_O[(size_t)(gr0 + 8) * 512 + (col >> 1)] =
            pkh(oacc[nt][2] * i1, oacc[nt][3] * i1);
    }
}

// =========================================================================
// LayerNorm: warp-per-row (R14). Grid = Mn/8 = 512, 256 threads.
// =========================================================================
__global__ void __launch_bounds__(256) ln_kernel(
    const float* __restrict__ P, const float* __restrict__ gw,
    const float* __restrict__ gb, float* __restrict__ out)
{
    const int lane = threadIdx.x & 31;
    const int row = blockIdx.x * 8 + (threadIdx.x >> 5);
    const float4* src = (const float4*)(P + (size_t)row * Dn);

    float4 v[8];
    float s = 0.f, ss = 0.f;
#pragma unroll
    for (int i = 0; i < 8; i++) {
        v[i] = src[lane + 32 * i];
        s  += v[i].x + v[i].y + v[i].z + v[i].w;
        ss += v[i].x * v[i].x + v[i].y * v[i].y
            + v[i].z * v[i].z + v[i].w * v[i].w;
    }
#pragma unroll
    for (int off = 16; off; off >>= 1) {
        s  += __shfl_xor_sync(0xffffffffu, s, off);
        ss += __shfl_xor_sync(0xffffffffu, ss, off);
    }
    const float mu  = s * (1.0f / Dn);
    const float var = ss * (1.0f / Dn) - mu * mu;
    const float rs  = rsqrtf(var + 1e-5f);

    float4* dst = (float4*)(out + (size_t)row * Dn);
#pragma unroll
    for (int i = 0; i < 8; i++) {
        const float4 gv = ((const float4*)gw)[lane + 32 * i];
        const float4 bv = ((const float4*)gb)[lane + 32 * i];
        float4 r;
        r.x = (v[i].x - mu) * rs * gv.x + bv.x;
        r.y = (v[i].y - mu) * rs * gv.y + bv.y;
        r.z = (v[i].z - mu) * rs * gv.z + bv.z;
        r.w = (v[i].w - mu) * rs * gv.w + bv.w;
        dst[lane + 32 * i] = r;
    }
}

// =========================================================================
// Host
// =========================================================================
typedef CUresult (*PFN_tmencode)(
    CUtensorMap*, CUtensorMapDataType, cuuint32_t, void*,
    const cuuint64_t*, const cuuint64_t*, const cuuint32_t*, const cuuint32_t*,
    CUtensorMapInterleave, CUtensorMapSwizzle, CUtensorMapL2promotion,
    CUtensorMapFloatOOBfill);

static void mkmap_f16(PFN_tmencode enc, CUtensorMap* tm, const void* ptr,
                      unsigned long long d0, unsigned long long d1,
                      unsigned long long stride_bytes, unsigned b0, unsigned b1)
{
    cuuint64_t dims[2] = {(cuuint64_t)d0, (cuuint64_t)d1};
    cuuint64_t str[1]  = {(cuuint64_t)stride_bytes};
    cuuint32_t box[2]  = {b0, b1};
    cuuint32_t es[2]   = {1, 1};
    enc(tm, CU_TENSOR_MAP_DATA_TYPE_FLOAT16, 2, (void*)ptr, dims, str, box, es,
        CU_TENSOR_MAP_INTERLEAVE_NONE, CU_TENSOR_MAP_SWIZZLE_128B,
        CU_TENSOR_MAP_L2_PROMOTION_L2_128B, CU_TENSOR_MAP_FLOAT_OOB_FILL_NONE);
}

extern "C" void kernel_launch(void* const* d_in, const int* in_sizes, int n_in,
                              void* d_out, int out_size)
{
    const float* x  = (const float*)d_in[0];
    const float* Wq = (const float*)d_in[1];
    const float* bq = (const float*)d_in[2];
    const float* Wk = (const float*)d_in[3];
    const float* bk = (const float*)d_in[4];
    const float* Wv = (const float*)d_in[5];
    const float* bv = (const float*)d_in[6];
    const float* Wo = (const float*)d_in[7];
    const float* bo = (const float*)d_in[8];
    const float* lg = (const float*)d_in[9];
    const float* lb = (const float*)d_in[10];
    float* out = (float*)d_out;

    void *gxb, *gwq, *gwk, *gwv, *gwo, *gq, *gk, *gv, *go, *gp;
    cudaGetSymbolAddress(&gxb, g_xb);
    cudaGetSymbolAddress(&gwq, g_Wqb);
    cudaGetSymbolAddress(&gwk, g_Wkb);
    cudaGetSymbolAddress(&gwv, g_Wvb);
    cudaGetSymbolAddress(&gwo, g_Wob);
    cudaGetSymbolAddress(&gq,  g_Q);
    cudaGetSymbolAddress(&gk,  g_K);
    cudaGetSymbolAddress(&gv,  g_V);
    cudaGetSymbolAddress(&go,  g_O);
    cudaGetSymbolAddress(&gp,  g_P);

    void* fp = nullptr;
    cudaDriverEntryPointQueryResult st;
    cudaGetDriverEntryPointByVersion("cuTensorMapEncodeTiled", &fp, 12000,
                                     cudaEnableDefault, &st);
    PFN_tmencode enc = (PFN_tmencode)fp;

    CUtensorMap tmX, tmO, tmWq, tmWk, tmWv, tmWo, tmQ, tmK, tmV;
    // activations [4096 m][1024 k] f16: box 64k x 256m
    mkmap_f16(enc, &tmX, gxb, 1024, 4096, 2048ULL, 64, 256);
    mkmap_f16(enc, &tmO, go,  1024, 4096, 2048ULL, 64, 256);
    // weights [1024 k][1024 n] f16: box 64n x 64k
    mkmap_f16(enc, &tmWq, gwq, 1024, 1024, 2048ULL, 64, 64);
    mkmap_f16(enc, &tmWk, gwk, 1024, 1024, 2048ULL, 64, 64);
    mkmap_f16(enc, &tmWv, gwv, 1024, 1024, 2048ULL, 64, 64);
    mkmap_f16(enc, &tmWo, gwo, 1024, 1024, 2048ULL, 64, 64);
    // Q/K/V [65536 rows][64 d] f16 (stride 128B)
    mkmap_f16(enc, &tmQ, gq, 64, (unsigned long long)Bn * Hn * Tn, 128ULL, 64, 128);
    mkmap_f16(enc, &tmK, gk, 64, (unsigned long long)Bn * Hn * Tn, 128ULL, 64, 64);
    mkmap_f16(enc, &tmV, gv, 64, (unsigned long long)Bn * Hn * Tn, 128ULL, 64, 64);

    cudaFuncSetAttribute(qkv_gemm, cudaFuncAttributeMaxDynamicSharedMemorySize,
                         GEMM_DSMEM);
    cudaFuncSetAttribute(oproj_gemm, cudaFuncAttributeMaxDynamicSharedMemorySize,
                         GEMM_DSMEM);
    cudaFuncSetAttribute(attn_tc, cudaFuncAttributeMaxDynamicSharedMemorySize,
                         ATT_DSMEM);

    cvt_f16<<<dim3(1024, 1, 8), 256>>>(x, Wq, Wk, Wv, Wo);

    qkv_gemm<<<dim3(Dn / 128, Mn / 256, 3), 512, GEMM_DSMEM>>>(
        tmX, tmWq, tmWk, tmWv, bq, bk, bv);

    attn_tc<<<dim3(Tn / 128, Bn * Hn), 256, ATT_DSMEM>>>(tmQ, tmK, tmV);

    oproj_gemm<<<dim3(Dn / 128, Mn / 256), 512, GEMM_DSMEM>>>(tmO, tmWo, bo, x);

    ln_kernel<<<Mn / 8, 256>>>((const float*)gp, lg, lb, out);
}